// round 16
// baseline (speedup 1.0000x reference)
#include <cuda_runtime.h>

#define NN 100000
#define EE 1600000
#define DD 64
#define GG 256
#define NPART 98   // ceil(NN/1024)
#define HH 50048   // pipeline split point (= 391*128, and HH*16 % 256 == 0)

typedef unsigned long long ull;

// ---- scratch (no allocs allowed) ----
__device__ int   g_is32;
__device__ int   g_deg[NN];
__device__ int   g_off[NN + 1];
__device__ int   g_part[128];
__device__ int   g_cursor[NN];
__device__ int   g_csr[EE];
__device__ float g_agg[NN * DD];
__device__ float g_hA[NN * DD];
__device__ float g_hB[NN * DD];

// ---- packed f32x2 helpers (FFMA2 path: only reachable via PTX) ----
__device__ __forceinline__ ull pk2(float x) {
    ull r;
    asm("mov.b64 %0, {%1, %1};" : "=l"(r) : "f"(x));
    return r;
}
__device__ __forceinline__ void fma2(ull& d, ull a, ull b) {
    asm("fma.rn.f32x2 %0, %1, %2, %0;" : "+l"(d) : "l"(a), "l"(b));
}
__device__ __forceinline__ void add2(ull& d, ull b) {
    asm("add.rn.f32x2 %0, %0, %1;" : "+l"(d) : "l"(b));
}
__device__ __forceinline__ float2 unpk(ull v) {
    float2 r;
    asm("mov.b64 {%0, %1}, %2;" : "=f"(r.x), "=f"(r.y) : "l"(v));
    return r;
}

// ---------------------------------------------------------------------------
// CSR build chain (unchanged from best kernel)
// ---------------------------------------------------------------------------
__global__ __launch_bounds__(256) void zero_detect_kernel(const unsigned long long* __restrict__ ei) {
    int i = blockIdx.x * 256 + threadIdx.x;
    if (i < NN) g_deg[i] = 0;
    if (blockIdx.x == 0) {
        int bad = (ei[threadIdx.x] >> 32) != 0ull;
        int any = __syncthreads_or(bad);
        if (threadIdx.x == 0) g_is32 = any;
    }
}

__global__ __launch_bounds__(256) void hist_kernel(const void* __restrict__ ei) {
    int e = blockIdx.x * 256 + threadIdx.x;
    if (e >= EE) return;
    int d;
    if (g_is32) d = __ldg(&((const int*)ei)[EE + e]);
    else        d = (int)__ldg(&((const long long*)ei)[EE + e]);
    atomicAdd(&g_deg[d], 1);
}

__global__ __launch_bounds__(1024) void scan1_kernel() {
    __shared__ int warpTot[32];
    int tid = threadIdx.x, lane = tid & 31, warp = tid >> 5;
    int i = blockIdx.x * 1024 + tid;
    int v = (i < NN) ? g_deg[i] : 0;
    int x = v;
#pragma unroll
    for (int o = 1; o < 32; o <<= 1) {
        int t = __shfl_up_sync(0xffffffffu, x, o);
        if (lane >= o) x += t;
    }
    if (lane == 31) warpTot[warp] = x;
    __syncthreads();
    if (warp == 0) {
        int w = warpTot[lane];
        int y = w;
#pragma unroll
        for (int o = 1; o < 32; o <<= 1) {
            int t = __shfl_up_sync(0xffffffffu, y, o);
            if (lane >= o) y += t;
        }
        warpTot[lane] = y - w;
        if (lane == 31 && blockIdx.x < NPART) g_part[blockIdx.x] = y;
    }
    __syncthreads();
    if (i < NN) g_off[i] = x - v + warpTot[warp];
}

__global__ __launch_bounds__(256) void scan23_kernel() {
    __shared__ int p[128];
    int tid = threadIdx.x;
    if (tid < 128) p[tid] = (tid < NPART) ? g_part[tid] : 0;
    __syncthreads();
    int v = (tid < 128) ? p[tid] : 0;
#pragma unroll
    for (int d = 1; d < 128; d <<= 1) {
        int t = (tid < 128 && tid >= d) ? p[tid - d] : 0;
        __syncthreads();
        if (tid < 128) p[tid] += t;
        __syncthreads();
    }
    if (tid < 128) p[tid] -= v;
    __syncthreads();
    int i = blockIdx.x * 256 + tid;
    if (i < NN) {
        int o = g_off[i] + p[i >> 10];
        g_off[i] = o;
        g_cursor[i] = o;
    }
    if (i == 0) g_off[NN] = EE;
}

__global__ __launch_bounds__(256) void fill_kernel(const void* __restrict__ ei) {
    int e = blockIdx.x * 256 + threadIdx.x;
    if (e >= EE) return;
    int s, d;
    if (g_is32) {
        const int* p = (const int*)ei;
        s = __ldg(&p[e]); d = __ldg(&p[EE + e]);
    } else {
        const long long* p = (const long long*)ei;
        s = (int)__ldg(&p[e]); d = (int)__ldg(&p[EE + e]);
    }
    int pos = atomicAdd(&g_cursor[d], 1);
    g_csr[pos] = s;
}

// ---------------------------------------------------------------------------
// gather body: z[node] = h[node] + sum_{s in csr[node]} h[s]
// 16 threads per node, one 16B column each; t indexes (node-nodeBase)*16+c.
// ---------------------------------------------------------------------------
__device__ __forceinline__ void gather_body(
    const ulonglong2* __restrict__ h, ulonglong2* __restrict__ z,
    int t, int nodeBase)
{
    int node = nodeBase + (t >> 4), c = t & 15;
    if (node >= NN) return;
    ulonglong2 acc = h[node * 16 + c];
    int i = g_off[node], end = g_off[node + 1];
    int s_next = (i < end) ? __ldg(&g_csr[i]) : 0;
    while (i < end) {
        int s = s_next;
        i++;
        if (i < end) s_next = __ldg(&g_csr[i]);
        ulonglong2 v = h[s * 16 + c];
        add2(acc.x, v.x);
        add2(acc.y, v.y);
    }
    z[node * 16 + c] = acc;
}

__global__ __launch_bounds__(256) void gather_kernel(
    const ulonglong2* __restrict__ h, ulonglong2* __restrict__ z, int nodeBase)
{
    gather_body(h, z, blockIdx.x * 256 + threadIdx.x, nodeBase);
}

// ---------------------------------------------------------------------------
// FFMA2 GEMM microkernel: acc2[8][2] (packed col pairs) = sZ(128x64,s68) @ sW(64x64)
// ---------------------------------------------------------------------------
__device__ __forceinline__ void mm_tile8(const float* __restrict__ sW,
                                         const float* __restrict__ sZ,
                                         ull acc2[8][2], int tx, int r0)
{
#pragma unroll
    for (int i = 0; i < 8; i++) { acc2[i][0] = 0ull; acc2[i][1] = 0ull; }

#pragma unroll 2
    for (int k4 = 0; k4 < 16; k4++) {
        ulonglong2 w[4];
#pragma unroll
        for (int kk = 0; kk < 4; kk++)
            w[kk] = *(const ulonglong2*)&sW[(k4 * 4 + kk) * 64 + tx * 4];
#pragma unroll
        for (int i = 0; i < 8; i++) {
            float4 zv = *(const float4*)&sZ[(r0 + i) * 68 + k4 * 4];
            ull zx = pk2(zv.x), zy = pk2(zv.y), zz = pk2(zv.z), zw = pk2(zv.w);
            fma2(acc2[i][0], zx, w[0].x); fma2(acc2[i][1], zx, w[0].y);
            fma2(acc2[i][0], zy, w[1].x); fma2(acc2[i][1], zy, w[1].y);
            fma2(acc2[i][0], zz, w[2].x); fma2(acc2[i][1], zz, w[2].y);
            fma2(acc2[i][0], zw, w[3].x); fma2(acc2[i][1], zw, w[3].y);
        }
    }
}

struct MlpS {
    float sW[64 * 64];
    float sZ[128 * 68];
    float b1s[64], b2s[64], fcs[64];
};

// ---------------------------------------------------------------------------
// MLP block body (node0 = first node of this 128-row tile):
//   y = relu(z @ W1 + b1) @ W2 + b2
//   fcw == null : hout[node] = relu?(y)
//   fcw != null : out[batch[node]] += dot(y, fcw)
// ---------------------------------------------------------------------------
__device__ __forceinline__ void mlp_body(
    MlpS& sm, int node0,
    const float* __restrict__ z,
    const float* __restrict__ w1, const float* __restrict__ b1,
    const float* __restrict__ w2, const float* __restrict__ b2,
    float* __restrict__ hout, int relu_out,
    const float* __restrict__ fcw, const void* __restrict__ batch,
    float* __restrict__ out)
{
    int tid = threadIdx.x;
    for (int i = tid; i < 4096; i += 256) sm.sW[i] = w1[i];
    if (tid < 64) {
        sm.b1s[tid] = b1[tid];
        sm.b2s[tid] = b2[tid];
        sm.fcs[tid] = fcw ? fcw[tid] : 0.f;
    }

#pragma unroll
    for (int j = 0; j < 8; j++) {
        int q = tid + j * 256;
        int r = q >> 4, c = q & 15;
        int node = node0 + r;
        float4 v = make_float4(0.f, 0.f, 0.f, 0.f);
        if (node < NN) v = ((const float4*)z)[node * 16 + c];
        *(float4*)&sm.sZ[r * 68 + c * 4] = v;
    }
    __syncthreads();

    int tx = tid & 15, ty = tid >> 4;
    int r0 = ty * 8;
    ull acc2[8][2];

    mm_tile8(sm.sW, sm.sZ, acc2, tx, r0);
    __syncthreads();  // all reads of W1 / z complete

    for (int i = tid; i < 4096; i += 256) sm.sW[i] = w2[i];
#pragma unroll
    for (int i = 0; i < 8; i++) {
        float2 a01 = unpk(acc2[i][0]);
        float2 a23 = unpk(acc2[i][1]);
        float4 hv;
        hv.x = fmaxf(a01.x + sm.b1s[tx * 4 + 0], 0.f);
        hv.y = fmaxf(a01.y + sm.b1s[tx * 4 + 1], 0.f);
        hv.z = fmaxf(a23.x + sm.b1s[tx * 4 + 2], 0.f);
        hv.w = fmaxf(a23.y + sm.b1s[tx * 4 + 3], 0.f);
        *(float4*)&sm.sZ[(r0 + i) * 68 + tx * 4] = hv;
    }
    __syncthreads();

    mm_tile8(sm.sW, sm.sZ, acc2, tx, r0);

    if (!fcw) {
#pragma unroll
        for (int i = 0; i < 8; i++) {
            int node = node0 + r0 + i;
            if (node < NN) {
                float2 a01 = unpk(acc2[i][0]);
                float2 a23 = unpk(acc2[i][1]);
                float4 o;
                o.x = a01.x + sm.b2s[tx * 4 + 0];
                o.y = a01.y + sm.b2s[tx * 4 + 1];
                o.z = a23.x + sm.b2s[tx * 4 + 2];
                o.w = a23.y + sm.b2s[tx * 4 + 3];
                if (relu_out) {
                    o.x = fmaxf(o.x, 0.f); o.y = fmaxf(o.y, 0.f);
                    o.z = fmaxf(o.z, 0.f); o.w = fmaxf(o.w, 0.f);
                }
                ((float4*)hout)[node * 16 + tx] = o;
            }
        }
    } else {
        // pool + FC epilogue: half-warp (16 lanes, same node) shuffle reduction
#pragma unroll
        for (int i = 0; i < 8; i++) {
            int node = node0 + r0 + i;
            float2 a01 = unpk(acc2[i][0]);
            float2 a23 = unpk(acc2[i][1]);
            float p = (a01.x + sm.b2s[tx * 4 + 0]) * sm.fcs[tx * 4 + 0]
                    + (a01.y + sm.b2s[tx * 4 + 1]) * sm.fcs[tx * 4 + 1]
                    + (a23.x + sm.b2s[tx * 4 + 2]) * sm.fcs[tx * 4 + 2]
                    + (a23.y + sm.b2s[tx * 4 + 3]) * sm.fcs[tx * 4 + 3];
#pragma unroll
            for (int o = 8; o; o >>= 1) p += __shfl_xor_sync(0xffffffffu, p, o);
            if (tx == 0 && node < NN) {
                int g;
                if (g_is32) g = __ldg(&((const int*)batch)[node]);
                else        g = (int)__ldg(&((const long long*)batch)[node]);
                atomicAdd(&out[g], p);
            }
        }
    }
}

// standalone MLP kernel (tail half of the pipeline)
__global__ __launch_bounds__(256, 2) void mlp_kernel(
    const float* __restrict__ z, int nodeBase,
    const float* __restrict__ w1, const float* __restrict__ b1,
    const float* __restrict__ w2, const float* __restrict__ b2,
    float* __restrict__ hout, int relu_out,
    const float* __restrict__ fcw, const void* __restrict__ batch,
    float* __restrict__ out)
{
    __shared__ MlpS sm;
    mlp_body(sm, nodeBase + blockIdx.x * 128, z, w1, b1, w2, b2,
             hout, relu_out, fcw, batch, out);
}

// ---------------------------------------------------------------------------
// fused pipeline kernel: mlp on nodes [0,HH) + gather on nodes [HH,NN).
// Roles striped (bid % 9 == 0 -> mlp, 391 of 3513 blocks) so every SM runs a
// mix: FMA-bound mlp blocks hide under LTS-bound gather blocks.
//   grid = 391 + 3122 = 3513 blocks
// ---------------------------------------------------------------------------
#define MLP_HALF_BLOCKS 391
#define GATHER_HALF_BLOCKS 3122
#define FUSED_BLOCKS (MLP_HALF_BLOCKS + GATHER_HALF_BLOCKS)

__global__ __launch_bounds__(256, 2) void fused_layer_kernel(
    const ulonglong2* __restrict__ h_in,   // gather source (layer input)
    ulonglong2* __restrict__ agg,          // gather dest / mlp z source
    const float* __restrict__ w1, const float* __restrict__ b1,
    const float* __restrict__ w2, const float* __restrict__ b2,
    float* __restrict__ hout, int relu_out,
    const float* __restrict__ fcw, const void* __restrict__ batch,
    float* __restrict__ out)
{
    __shared__ MlpS sm;
    int bid = blockIdx.x;
    if (bid % 9 == 0 && bid / 9 < MLP_HALF_BLOCKS) {
        int m = bid / 9;
        mlp_body(sm, m * 128, (const float*)agg, w1, b1, w2, b2,
                 hout, relu_out, fcw, batch, out);
    } else {
        int g = bid - (bid / 9 + 1);
        gather_body(h_in, agg, g * 256 + threadIdx.x, HH);
    }
}

// ---------------------------------------------------------------------------
__global__ void init_out_kernel(float* __restrict__ out, const float* __restrict__ fcb) {
    if (threadIdx.x < GG) out[threadIdx.x] = fcb[0];
}

// ---------------------------------------------------------------------------
extern "C" void kernel_launch(void* const* d_in, const int* in_sizes, int n_in,
                              void* d_out, int out_size)
{
    const float* x   = (const float*)d_in[0];
    const void*  ei  = d_in[1];
    const void*  bat = d_in[2];
    const float* w1[3], *b1[3], *w2[3], *b2[3];
    for (int l = 0; l < 3; l++) {
        w1[l] = (const float*)d_in[3 + 4 * l];
        b1[l] = (const float*)d_in[4 + 4 * l];
        w2[l] = (const float*)d_in[5 + 4 * l];
        b2[l] = (const float*)d_in[6 + 4 * l];
    }
    const float* fcw = (const float*)d_in[15];
    const float* fcb = (const float*)d_in[16];
    float* out = (float*)d_out;

    float *agg, *hA, *hB;
    cudaGetSymbolAddress((void**)&agg, g_agg);
    cudaGetSymbolAddress((void**)&hA,  g_hA);
    cudaGetSymbolAddress((void**)&hB,  g_hB);

    const int edge_blocks = (EE + 255) / 256;       // 6250
    const int node_blocks = (NN + 255) / 256;       // 391
    const int g1_blocks   = HH * 16 / 256;          // 3128 (first-half gather)
    const int m2_blocks   = (NN - HH + 127) / 128;  // 391 (tail-half mlp)

    // ---- CSR-by-destination build ----
    zero_detect_kernel<<<node_blocks, 256>>>((const unsigned long long*)ei);
    hist_kernel<<<edge_blocks, 256>>>(ei);
    scan1_kernel<<<NPART, 1024>>>();
    scan23_kernel<<<node_blocks, 256>>>();
    fill_kernel<<<edge_blocks, 256>>>(ei);

    init_out_kernel<<<1, 256>>>(out, fcb);

    // ---- layer 0: x -> hA ----
    gather_kernel<<<g1_blocks, 256>>>((const ulonglong2*)x, (ulonglong2*)agg, 0);
    fused_layer_kernel<<<FUSED_BLOCKS, 256>>>((const ulonglong2*)x, (ulonglong2*)agg,
        w1[0], b1[0], w2[0], b2[0], hA, 1, (const float*)0, (const void*)0, (float*)0);
    mlp_kernel<<<m2_blocks, 256>>>((const float*)agg, HH,
        w1[0], b1[0], w2[0], b2[0], hA, 1, (const float*)0, (const void*)0, (float*)0);

    // ---- layer 1: hA -> hB ----
    gather_kernel<<<g1_blocks, 256>>>((const ulonglong2*)hA, (ulonglong2*)agg, 0);
    fused_layer_kernel<<<FUSED_BLOCKS, 256>>>((const ulonglong2*)hA, (ulonglong2*)agg,
        w1[1], b1[1], w2[1], b2[1], hB, 1, (const float*)0, (const void*)0, (float*)0);
    mlp_kernel<<<m2_blocks, 256>>>((const float*)agg, HH,
        w1[1], b1[1], w2[1], b2[1], hB, 1, (const float*)0, (const void*)0, (float*)0);

    // ---- layer 2: hB -> pooled FC output ----
    gather_kernel<<<g1_blocks, 256>>>((const ulonglong2*)hB, (ulonglong2*)agg, 0);
    fused_layer_kernel<<<FUSED_BLOCKS, 256>>>((const ulonglong2*)hB, (ulonglong2*)agg,
        w1[2], b1[2], w2[2], b2[2], (float*)0, 0, fcw, bat, out);
    mlp_kernel<<<m2_blocks, 256>>>((const float*)agg, HH,
        w1[2], b1[2], w2[2], b2[2], (float*)0, 0, fcw, bat, out);
}

// round 17
// speedup vs baseline: 1.3254x; 1.3254x over previous
#include <cuda_runtime.h>

#define NN 100000
#define EE 1600000
#define DD 64
#define GG 256
#define NPART 98   // ceil(NN/1024)

typedef unsigned long long ull;

// ---- scratch (no allocs allowed) ----
__device__ int   g_is32;
__device__ int   g_deg[NN];
__device__ int   g_off[NN + 1];
__device__ int   g_part[128];
__device__ int   g_rank[EE];
__device__ int   g_csr[EE];
__device__ float g_agg[NN * DD];
__device__ float g_hA[NN * DD];
__device__ float g_hB[NN * DD];

// ---- packed f32x2 helpers (FFMA2 path: only reachable via PTX) ----
__device__ __forceinline__ ull pk2(float x) {
    ull r;
    asm("mov.b64 %0, {%1, %1};" : "=l"(r) : "f"(x));
    return r;
}
__device__ __forceinline__ void fma2(ull& d, ull a, ull b) {
    asm("fma.rn.f32x2 %0, %1, %2, %0;" : "+l"(d) : "l"(a), "l"(b));
}
__device__ __forceinline__ void add2(ull& d, ull b) {
    asm("add.rn.f32x2 %0, %0, %1;" : "+l"(d) : "l"(b));
}
__device__ __forceinline__ float2 unpk(ull v) {
    float2 r;
    asm("mov.b64 {%0, %1}, %2;" : "=f"(r.x), "=f"(r.y) : "l"(v));
    return r;
}

// ---------------------------------------------------------------------------
// zero degree array; block 0 detects index dtype (int64 data has all-zero high
// words among the first 256 qwords); block 1 initializes out[g] = fc_b.
// ---------------------------------------------------------------------------
__global__ __launch_bounds__(256) void zero_detect_kernel(
    const unsigned long long* __restrict__ ei,
    float* __restrict__ out, const float* __restrict__ fcb)
{
    int i = blockIdx.x * 256 + threadIdx.x;
    if (i < NN) g_deg[i] = 0;
    if (blockIdx.x == 0) {
        int bad = (ei[threadIdx.x] >> 32) != 0ull;
        int any = __syncthreads_or(bad);
        if (threadIdx.x == 0) g_is32 = any;
    } else if (blockIdx.x == 1) {
        if (threadIdx.x < GG) out[threadIdx.x] = fcb[0];
    }
}

// histogram of destinations; the atomic's return value IS the edge's rank
// within its destination bucket — store it so fill needs no atomic.
__global__ __launch_bounds__(256) void hist_kernel(const void* __restrict__ ei) {
    int e = blockIdx.x * 256 + threadIdx.x;
    if (e >= EE) return;
    int d;
    if (g_is32) d = __ldg(&((const int*)ei)[EE + e]);
    else        d = (int)__ldg(&((const long long*)ei)[EE + e]);
    g_rank[e] = atomicAdd(&g_deg[d], 1);
}

// ---- scan level 1: per-1024-block exclusive scan via warp shuffles ----
__global__ __launch_bounds__(1024) void scan1_kernel() {
    __shared__ int warpTot[32];
    int tid = threadIdx.x, lane = tid & 31, warp = tid >> 5;
    int i = blockIdx.x * 1024 + tid;
    int v = (i < NN) ? g_deg[i] : 0;
    int x = v;
#pragma unroll
    for (int o = 1; o < 32; o <<= 1) {
        int t = __shfl_up_sync(0xffffffffu, x, o);
        if (lane >= o) x += t;
    }
    if (lane == 31) warpTot[warp] = x;
    __syncthreads();
    if (warp == 0) {
        int w = warpTot[lane];
        int y = w;
#pragma unroll
        for (int o = 1; o < 32; o <<= 1) {
            int t = __shfl_up_sync(0xffffffffu, y, o);
            if (lane >= o) y += t;
        }
        warpTot[lane] = y - w;
        if (lane == 31 && blockIdx.x < NPART) g_part[blockIdx.x] = y;
    }
    __syncthreads();
    if (i < NN) g_off[i] = x - v + warpTot[warp];
}

// ---- scan levels 2+3 merged: every block redundantly scans the 98 partials
//      (parallel Hillis-Steele over 128 threads) ----
__global__ __launch_bounds__(256) void scan23_kernel() {
    __shared__ int p[128];
    int tid = threadIdx.x;
    if (tid < 128) p[tid] = (tid < NPART) ? g_part[tid] : 0;
    __syncthreads();
    int v = (tid < 128) ? p[tid] : 0;
#pragma unroll
    for (int d = 1; d < 128; d <<= 1) {
        int t = (tid < 128 && tid >= d) ? p[tid - d] : 0;
        __syncthreads();
        if (tid < 128) p[tid] += t;
        __syncthreads();
    }
    if (tid < 128) p[tid] -= v;
    __syncthreads();
    int i = blockIdx.x * 256 + tid;
    if (i < NN) g_off[i] = g_off[i] + p[i >> 10];
    if (i == 0) g_off[NN] = EE;
}

// atomic-free fill: pos = off[dst] + rank[e]
__global__ __launch_bounds__(256) void fill_kernel(const void* __restrict__ ei) {
    int e = blockIdx.x * 256 + threadIdx.x;
    if (e >= EE) return;
    int s, d;
    if (g_is32) {
        const int* p = (const int*)ei;
        s = __ldg(&p[e]); d = __ldg(&p[EE + e]);
    } else {
        const long long* p = (const long long*)ei;
        s = (int)__ldg(&p[e]); d = (int)__ldg(&p[EE + e]);
    }
    g_csr[__ldg(&g_off[d]) + g_rank[e]] = s;
}

// ---------------------------------------------------------------------------
// gather: z[d] = h[d] + sum_{s in csr[d]} h[s].  16 threads per node, one
// 16-byte column each; rows L2-resident, accumulate via packed f32x2 adds.
// ---------------------------------------------------------------------------
__global__ __launch_bounds__(256) void gather_kernel(
    const ulonglong2* __restrict__ h, ulonglong2* __restrict__ z)
{
    int t = blockIdx.x * 256 + threadIdx.x;
    if (t >= NN * 16) return;
    int node = t >> 4, c = t & 15;
    ulonglong2 acc = h[node * 16 + c];          // self term (eps = 0)
    int i = g_off[node], end = g_off[node + 1];
    int s_next = (i < end) ? __ldg(&g_csr[i]) : 0;
    while (i < end) {
        int s = s_next;
        i++;
        if (i < end) s_next = __ldg(&g_csr[i]);  // prefetch next index
        ulonglong2 v = h[s * 16 + c];
        add2(acc.x, v.x);
        add2(acc.y, v.y);
    }
    z[node * 16 + c] = acc;
}

// ---------------------------------------------------------------------------
// GEMM microkernel (FFMA2): acc2[8][2] (packed col pairs) = sZ(128x64,s68) @ sW(64x64)
// ---------------------------------------------------------------------------
__device__ __forceinline__ void mm_tile8(const float* __restrict__ sW,
                                         const float* __restrict__ sZ,
                                         ull acc2[8][2], int tx, int r0)
{
#pragma unroll
    for (int i = 0; i < 8; i++) { acc2[i][0] = 0ull; acc2[i][1] = 0ull; }

#pragma unroll 2
    for (int k4 = 0; k4 < 16; k4++) {
        ulonglong2 w[4];
#pragma unroll
        for (int kk = 0; kk < 4; kk++)
            w[kk] = *(const ulonglong2*)&sW[(k4 * 4 + kk) * 64 + tx * 4];
#pragma unroll
        for (int i = 0; i < 8; i++) {
            float4 zv = *(const float4*)&sZ[(r0 + i) * 68 + k4 * 4];
            ull zx = pk2(zv.x), zy = pk2(zv.y), zz = pk2(zv.z), zw = pk2(zv.w);
            fma2(acc2[i][0], zx, w[0].x); fma2(acc2[i][1], zx, w[0].y);
            fma2(acc2[i][0], zy, w[1].x); fma2(acc2[i][1], zy, w[1].y);
            fma2(acc2[i][0], zz, w[2].x); fma2(acc2[i][1], zz, w[2].y);
            fma2(acc2[i][0], zw, w[3].x); fma2(acc2[i][1], zw, w[3].y);
        }
    }
}

// ---------------------------------------------------------------------------
// MLP: y = relu(z @ W1 + b1) @ W2 + b2.  128-node tile per block.
//   fcw == null : hout[node] = relu?(y)
//   fcw != null : out[batch[node]] += dot(y, fcw)   (global_add_pool + FC)
// ---------------------------------------------------------------------------
__global__ __launch_bounds__(256, 2) void mlp_kernel(
    const float* __restrict__ z,
    const float* __restrict__ w1, const float* __restrict__ b1,
    const float* __restrict__ w2, const float* __restrict__ b2,
    float* __restrict__ hout, int relu_out,
    const float* __restrict__ fcw, const void* __restrict__ batch,
    float* __restrict__ out)
{
    __shared__ float sW[64 * 64];
    __shared__ float sZ[128 * 68];
    __shared__ float sB1[64];
    __shared__ float sB2[64];
    __shared__ float sFC[64];

    int tid = threadIdx.x;
    for (int i = tid; i < 4096; i += 256) sW[i] = w1[i];
    if (tid < 64) {
        sB1[tid] = b1[tid];
        sB2[tid] = b2[tid];
        sFC[tid] = fcw ? fcw[tid] : 0.f;
    }

    int node0 = blockIdx.x * 128;
#pragma unroll
    for (int j = 0; j < 8; j++) {
        int q = tid + j * 256;
        int r = q >> 4, c = q & 15;
        int node = node0 + r;
        float4 v = make_float4(0.f, 0.f, 0.f, 0.f);
        if (node < NN) v = ((const float4*)z)[node * 16 + c];
        *(float4*)&sZ[r * 68 + c * 4] = v;
    }
    __syncthreads();

    int tx = tid & 15, ty = tid >> 4;
    int r0 = ty * 8;
    ull acc2[8][2];

    mm_tile8(sW, sZ, acc2, tx, r0);
    __syncthreads();  // all reads of W1 / z complete

    for (int i = tid; i < 4096; i += 256) sW[i] = w2[i];
#pragma unroll
    for (int i = 0; i < 8; i++) {
        float2 a01 = unpk(acc2[i][0]);
        float2 a23 = unpk(acc2[i][1]);
        float4 hv;
        hv.x = fmaxf(a01.x + sB1[tx * 4 + 0], 0.f);
        hv.y = fmaxf(a01.y + sB1[tx * 4 + 1], 0.f);
        hv.z = fmaxf(a23.x + sB1[tx * 4 + 2], 0.f);
        hv.w = fmaxf(a23.y + sB1[tx * 4 + 3], 0.f);
        *(float4*)&sZ[(r0 + i) * 68 + tx * 4] = hv;
    }
    __syncthreads();

    mm_tile8(sW, sZ, acc2, tx, r0);

    if (!fcw) {
#pragma unroll
        for (int i = 0; i < 8; i++) {
            int node = node0 + r0 + i;
            if (node < NN) {
                float2 a01 = unpk(acc2[i][0]);
                float2 a23 = unpk(acc2[i][1]);
                float4 o;
                o.x = a01.x + sB2[tx * 4 + 0];
                o.y = a01.y + sB2[tx * 4 + 1];
                o.z = a23.x + sB2[tx * 4 + 2];
                o.w = a23.y + sB2[tx * 4 + 3];
                if (relu_out) {
                    o.x = fmaxf(o.x, 0.f); o.y = fmaxf(o.y, 0.f);
                    o.z = fmaxf(o.z, 0.f); o.w = fmaxf(o.w, 0.f);
                }
                ((float4*)hout)[node * 16 + tx] = o;
            }
        }
    } else {
        // pool + FC epilogue: half-warp (16 lanes, same node) shuffle reduction
#pragma unroll
        for (int i = 0; i < 8; i++) {
            int node = node0 + r0 + i;
            float2 a01 = unpk(acc2[i][0]);
            float2 a23 = unpk(acc2[i][1]);
            float p = (a01.x + sB2[tx * 4 + 0]) * sFC[tx * 4 + 0]
                    + (a01.y + sB2[tx * 4 + 1]) * sFC[tx * 4 + 1]
                    + (a23.x + sB2[tx * 4 + 2]) * sFC[tx * 4 + 2]
                    + (a23.y + sB2[tx * 4 + 3]) * sFC[tx * 4 + 3];
#pragma unroll
            for (int o = 8; o; o >>= 1) p += __shfl_xor_sync(0xffffffffu, p, o);
            if (tx == 0 && node < NN) {
                int g;
                if (g_is32) g = __ldg(&((const int*)batch)[node]);
                else        g = (int)__ldg(&((const long long*)batch)[node]);
                atomicAdd(&out[g], p);
            }
        }
    }
}

// ---------------------------------------------------------------------------
extern "C" void kernel_launch(void* const* d_in, const int* in_sizes, int n_in,
                              void* d_out, int out_size)
{
    const float* x   = (const float*)d_in[0];
    const void*  ei  = d_in[1];
    const void*  bat = d_in[2];
    const float* w1[3], *b1[3], *w2[3], *b2[3];
    for (int l = 0; l < 3; l++) {
        w1[l] = (const float*)d_in[3 + 4 * l];
        b1[l] = (const float*)d_in[4 + 4 * l];
        w2[l] = (const float*)d_in[5 + 4 * l];
        b2[l] = (const float*)d_in[6 + 4 * l];
    }
    const float* fcw = (const float*)d_in[15];
    const float* fcb = (const float*)d_in[16];
    float* out = (float*)d_out;

    float *agg, *hA, *hB;
    cudaGetSymbolAddress((void**)&agg, g_agg);
    cudaGetSymbolAddress((void**)&hA,  g_hA);
    cudaGetSymbolAddress((void**)&hB,  g_hB);

    const int edge_blocks   = (EE + 255) / 256;       // 6250
    const int node_blocks   = (NN + 255) / 256;       // 391
    const int gather_blocks = (NN * 16 + 255) / 256;  // 6250
    const int mlp_blocks    = (NN + 127) / 128;       // 782

    // ---- CSR-by-destination build (atomic-free fill via rank trick) ----
    zero_detect_kernel<<<node_blocks, 256>>>((const unsigned long long*)ei, out, fcb);
    hist_kernel<<<edge_blocks, 256>>>(ei);
    scan1_kernel<<<NPART, 1024>>>();
    scan23_kernel<<<node_blocks, 256>>>();
    fill_kernel<<<edge_blocks, 256>>>(ei);

    // ---- layer 0 ----
    gather_kernel<<<gather_blocks, 256>>>((const ulonglong2*)x, (ulonglong2*)agg);
    mlp_kernel<<<mlp_blocks, 256>>>(agg, w1[0], b1[0], w2[0], b2[0], hA, 1,
                                    (const float*)0, (const void*)0, (float*)0);
    // ---- layer 1 ----
    gather_kernel<<<gather_blocks, 256>>>((const ulonglong2*)hA, (ulonglong2*)agg);
    mlp_kernel<<<mlp_blocks, 256>>>(agg, w1[1], b1[1], w2[1], b2[1], hB, 1,
                                    (const float*)0, (const void*)0, (float*)0);
    // ---- layer 2: MLP + fused global_add_pool + FC ----
    gather_kernel<<<gather_blocks, 256>>>((const ulonglong2*)hB, (ulonglong2*)agg);
    mlp_kernel<<<mlp_blocks, 256>>>(agg, w1[2], b1[2], w2[2], b2[2], (float*)0, 0,
                                    fcw, bat, out);
}